// round 2
// baseline (speedup 1.0000x reference)
#include <cuda_runtime.h>
#include <cuda_bf16.h>

// Problem constants (fixed shapes per reference)
#define NN 16384      // nodes
#define EE 262144     // edges (before self loops)
#define H1C 256       // hidden_dim1
#define DD 512        // 2*H1 = D_IN = gat2 channels
#define NEG_SLOPE 0.2f

// ---------------- device scratch (no allocations allowed) ----------------
__device__ float g_h0[NN * H1C];          // relu(x@W_fc+b_fc)      16 MB
__device__ float g_g1[(size_t)NN * DD];   // h0@W1 (pre-aggregate)  32 MB
__device__ float g_h1[(size_t)NN * DD];   // relu(gat1 out)         32 MB
__device__ float g_g2[(size_t)NN * DD];   // h1@W2                  32 MB
__device__ float g_al1[NN * 4];           // per node: s0,s1,d0,d1
__device__ float g_al2[NN * 2];           // per node: s,d
__device__ int   g_deg[NN];
__device__ int   g_cursor[NN];
__device__ int   g_off[NN + 1];
__device__ int   g_esrc[EE];
__device__ float g_alpha1[(size_t)EE * 2];
__device__ float g_salpha1[NN * 2];
__device__ float g_alpha2[EE];
__device__ float g_salpha2[NN];

// ---------------- CSR construction ----------------
__global__ void zero_kernel() {
    int i = blockIdx.x * blockDim.x + threadIdx.x;
    if (i < NN) { g_deg[i] = 0; g_cursor[i] = 0; }
}

__global__ void count_kernel(const int* __restrict__ adj) {
    int i = blockIdx.x * blockDim.x + threadIdx.x;
    if (i < EE) {
        int dst = adj[EE + i];
        atomicAdd(&g_deg[dst], 1);
    }
}

// exclusive scan of g_deg (16384) -> g_off; single block of 256 threads, 64 each
__global__ void scan_kernel() {
    int t = threadIdx.x;
    int base_i = t * 64;
    int sum = 0;
    #pragma unroll 4
    for (int k = 0; k < 64; k++) sum += g_deg[base_i + k];
    __shared__ int part[256];
    part[t] = sum;
    __syncthreads();
    for (int s = 1; s < 256; s <<= 1) {
        int v = (t >= s) ? part[t - s] : 0;
        __syncthreads();
        part[t] += v;
        __syncthreads();
    }
    int run = (t > 0) ? part[t - 1] : 0;
    for (int k = 0; k < 64; k++) {
        g_off[base_i + k] = run;
        run += g_deg[base_i + k];
    }
    if (t == 255) g_off[NN] = run;
}

__global__ void scatter_kernel(const int* __restrict__ adj) {
    int i = blockIdx.x * blockDim.x + threadIdx.x;
    if (i < EE) {
        int src = adj[i];
        int dst = adj[EE + i];
        int p = g_off[dst] + atomicAdd(&g_cursor[dst], 1);
        g_esrc[p] = src;
    }
}

// ---------------- SGEMM: C = act(A[M,K] @ B[K,N] + bias) ----------------
// 128x128 tile, BK=8, 256 threads, 8x8 microtile.
template <bool RELU, bool HAS_BIAS>
__global__ __launch_bounds__(256) void sgemm_kernel(
    const float* __restrict__ A, const float* __restrict__ B,
    const float* __restrict__ bias, float* __restrict__ C,
    int M, int N, int K)
{
    __shared__ float As[8][128];
    __shared__ float Bs[8][128];
    const int tid = threadIdx.x;
    const int brow = blockIdx.y * 128;
    const int bcol = blockIdx.x * 128;

    const int arow = tid >> 1;          // 0..127
    const int acol = (tid & 1) * 4;     // 0 or 4
    const int brl  = tid >> 5;          // 0..7
    const int bcl  = (tid & 31) * 4;    // 0..124

    const int ty = (tid >> 4) * 8;
    const int tx = (tid & 15) * 8;

    float acc[8][8];
    #pragma unroll
    for (int i = 0; i < 8; i++)
        #pragma unroll
        for (int j = 0; j < 8; j++) acc[i][j] = 0.f;

    for (int k0 = 0; k0 < K; k0 += 8) {
        float4 av = *(const float4*)(A + (size_t)(brow + arow) * K + k0 + acol);
        As[acol + 0][arow] = av.x;
        As[acol + 1][arow] = av.y;
        As[acol + 2][arow] = av.z;
        As[acol + 3][arow] = av.w;
        float4 bv = *(const float4*)(B + (size_t)(k0 + brl) * N + bcol + bcl);
        *(float4*)&Bs[brl][bcl] = bv;
        __syncthreads();

        #pragma unroll
        for (int k = 0; k < 8; k++) {
            float a[8], b[8];
            #pragma unroll
            for (int i = 0; i < 8; i++) a[i] = As[k][ty + i];
            #pragma unroll
            for (int j = 0; j < 8; j++) b[j] = Bs[k][tx + j];
            #pragma unroll
            for (int i = 0; i < 8; i++)
                #pragma unroll
                for (int j = 0; j < 8; j++)
                    acc[i][j] = fmaf(a[i], b[j], acc[i][j]);
        }
        __syncthreads();
    }

    #pragma unroll
    for (int i = 0; i < 8; i++) {
        float* crow = C + (size_t)(brow + ty + i) * N + bcol + tx;
        float v[8];
        #pragma unroll
        for (int j = 0; j < 8; j++) {
            v[j] = acc[i][j];
            if (HAS_BIAS) v[j] += bias[bcol + tx + j];
            if (RELU) v[j] = fmaxf(v[j], 0.f);
        }
        *(float4*)(crow)     = make_float4(v[0], v[1], v[2], v[3]);
        *(float4*)(crow + 4) = make_float4(v[4], v[5], v[6], v[7]);
    }
}

// ---------------- attention scalars ----------------
// al1: per node, s0,s1 (src-attn per head), d0,d1 (dst-attn per head).
// a1_src flat [2*256] matches g1 row layout (head-major), so flat float4 dot works.
__global__ void al1_kernel(const float* __restrict__ a_src,
                           const float* __restrict__ a_dst)
{
    int gw = (blockIdx.x * blockDim.x + threadIdx.x) >> 5;
    if (gw >= NN) return;
    int lane = threadIdx.x & 31;
    const float4* row = (const float4*)(g_g1 + (size_t)gw * DD);
    const float4* as4 = (const float4*)a_src;
    const float4* ad4 = (const float4*)a_dst;
    float s0 = 0.f, s1 = 0.f, d0 = 0.f, d1 = 0.f;
    for (int c = lane; c < 128; c += 32) {
        float4 v = row[c];
        float4 a = as4[c];
        float4 b = ad4[c];
        float sv = v.x * a.x + v.y * a.y + v.z * a.z + v.w * a.w;
        float dv = v.x * b.x + v.y * b.y + v.z * b.z + v.w * b.w;
        if (c < 64) { s0 += sv; d0 += dv; } else { s1 += sv; d1 += dv; }
    }
    #pragma unroll
    for (int o = 16; o; o >>= 1) {
        s0 += __shfl_down_sync(0xffffffffu, s0, o);
        s1 += __shfl_down_sync(0xffffffffu, s1, o);
        d0 += __shfl_down_sync(0xffffffffu, d0, o);
        d1 += __shfl_down_sync(0xffffffffu, d1, o);
    }
    if (lane == 0) {
        g_al1[gw * 4 + 0] = s0;
        g_al1[gw * 4 + 1] = s1;
        g_al1[gw * 4 + 2] = d0;
        g_al1[gw * 4 + 3] = d1;
    }
}

__global__ void al2_kernel(const float* __restrict__ a_src,
                           const float* __restrict__ a_dst)
{
    int gw = (blockIdx.x * blockDim.x + threadIdx.x) >> 5;
    if (gw >= NN) return;
    int lane = threadIdx.x & 31;
    const float4* row = (const float4*)(g_g2 + (size_t)gw * DD);
    const float4* as4 = (const float4*)a_src;
    const float4* ad4 = (const float4*)a_dst;
    float s = 0.f, d = 0.f;
    for (int c = lane; c < 128; c += 32) {
        float4 v = row[c];
        float4 a = as4[c];
        float4 b = ad4[c];
        s += v.x * a.x + v.y * a.y + v.z * a.z + v.w * a.w;
        d += v.x * b.x + v.y * b.y + v.z * b.z + v.w * b.w;
    }
    #pragma unroll
    for (int o = 16; o; o >>= 1) {
        s += __shfl_down_sync(0xffffffffu, s, o);
        d += __shfl_down_sync(0xffffffffu, d, o);
    }
    if (lane == 0) {
        g_al2[gw * 2 + 0] = s;
        g_al2[gw * 2 + 1] = d;
    }
}

__device__ __forceinline__ float lrelu(float x) {
    return x > 0.f ? x : NEG_SLOPE * x;
}

// ---------------- edge softmax (warp per node, incl. self loop) ----------------
__global__ void alpha1_kernel() {
    int n = (blockIdx.x * blockDim.x + threadIdx.x) >> 5;
    if (n >= NN) return;
    int lane = threadIdx.x & 31;
    int o = g_off[n];
    int cnt = g_off[n + 1] - o;
    float dd0 = g_al1[n * 4 + 2];
    float dd1 = g_al1[n * 4 + 3];

    float m0 = -1e30f, m1 = -1e30f;
    for (int i = lane; i <= cnt; i += 32) {
        int s = (i < cnt) ? g_esrc[o + i] : n;
        float e0 = lrelu(g_al1[s * 4 + 0] + dd0);
        float e1 = lrelu(g_al1[s * 4 + 1] + dd1);
        m0 = fmaxf(m0, e0);
        m1 = fmaxf(m1, e1);
    }
    #pragma unroll
    for (int x = 16; x; x >>= 1) {
        m0 = fmaxf(m0, __shfl_xor_sync(0xffffffffu, m0, x));
        m1 = fmaxf(m1, __shfl_xor_sync(0xffffffffu, m1, x));
    }
    float sum0 = 0.f, sum1 = 0.f;
    for (int i = lane; i <= cnt; i += 32) {
        int s = (i < cnt) ? g_esrc[o + i] : n;
        sum0 += expf(lrelu(g_al1[s * 4 + 0] + dd0) - m0);
        sum1 += expf(lrelu(g_al1[s * 4 + 1] + dd1) - m1);
    }
    #pragma unroll
    for (int x = 16; x; x >>= 1) {
        sum0 += __shfl_xor_sync(0xffffffffu, sum0, x);
        sum1 += __shfl_xor_sync(0xffffffffu, sum1, x);
    }
    float inv0 = 1.f / (sum0 + 1e-16f);
    float inv1 = 1.f / (sum1 + 1e-16f);
    for (int i = lane; i <= cnt; i += 32) {
        int s = (i < cnt) ? g_esrc[o + i] : n;
        float a0 = expf(lrelu(g_al1[s * 4 + 0] + dd0) - m0) * inv0;
        float a1 = expf(lrelu(g_al1[s * 4 + 1] + dd1) - m1) * inv1;
        if (i < cnt) {
            g_alpha1[(size_t)(o + i) * 2 + 0] = a0;
            g_alpha1[(size_t)(o + i) * 2 + 1] = a1;
        } else {
            g_salpha1[n * 2 + 0] = a0;
            g_salpha1[n * 2 + 1] = a1;
        }
    }
}

__global__ void alpha2_kernel() {
    int n = (blockIdx.x * blockDim.x + threadIdx.x) >> 5;
    if (n >= NN) return;
    int lane = threadIdx.x & 31;
    int o = g_off[n];
    int cnt = g_off[n + 1] - o;
    float dd = g_al2[n * 2 + 1];

    float m = -1e30f;
    for (int i = lane; i <= cnt; i += 32) {
        int s = (i < cnt) ? g_esrc[o + i] : n;
        m = fmaxf(m, lrelu(g_al2[s * 2] + dd));
    }
    #pragma unroll
    for (int x = 16; x; x >>= 1)
        m = fmaxf(m, __shfl_xor_sync(0xffffffffu, m, x));
    float sum = 0.f;
    for (int i = lane; i <= cnt; i += 32) {
        int s = (i < cnt) ? g_esrc[o + i] : n;
        sum += expf(lrelu(g_al2[s * 2] + dd) - m);
    }
    #pragma unroll
    for (int x = 16; x; x >>= 1)
        sum += __shfl_xor_sync(0xffffffffu, sum, x);
    float inv = 1.f / (sum + 1e-16f);
    for (int i = lane; i <= cnt; i += 32) {
        int s = (i < cnt) ? g_esrc[o + i] : n;
        float a = expf(lrelu(g_al2[s * 2] + dd) - m) * inv;
        if (i < cnt) g_alpha2[o + i] = a;
        else g_salpha2[n] = a;
    }
}

// ---------------- aggregation (block of 128 threads per node) ----------------
// gat1: heads=2, channel layout head-major [2*256]; head = col/256
__global__ __launch_bounds__(128) void agg1_kernel(const float* __restrict__ b1) {
    int n = blockIdx.x;
    int tid = threadIdx.x;             // 0..127, float4 column
    int o = g_off[n];
    int cnt = g_off[n + 1] - o;
    int head = tid >> 6;               // tid<64 -> head0

    __shared__ int   ssrc[128];
    __shared__ float sal[128 * 2];

    float4 acc = make_float4(0.f, 0.f, 0.f, 0.f);
    for (int base = 0; base < cnt; base += 128) {
        int m = min(128, cnt - base);
        if (tid < m) {
            ssrc[tid] = g_esrc[o + base + tid];
            sal[tid * 2 + 0] = g_alpha1[(size_t)(o + base + tid) * 2 + 0];
            sal[tid * 2 + 1] = g_alpha1[(size_t)(o + base + tid) * 2 + 1];
        }
        __syncthreads();
        for (int j = 0; j < m; j++) {
            float a = sal[j * 2 + head];
            const float4* r = (const float4*)(g_g1 + (size_t)ssrc[j] * DD);
            float4 v = r[tid];
            acc.x = fmaf(a, v.x, acc.x);
            acc.y = fmaf(a, v.y, acc.y);
            acc.z = fmaf(a, v.z, acc.z);
            acc.w = fmaf(a, v.w, acc.w);
        }
        __syncthreads();
    }
    // self loop
    {
        float a = g_salpha1[n * 2 + head];
        float4 v = ((const float4*)(g_g1 + (size_t)n * DD))[tid];
        acc.x = fmaf(a, v.x, acc.x);
        acc.y = fmaf(a, v.y, acc.y);
        acc.z = fmaf(a, v.z, acc.z);
        acc.w = fmaf(a, v.w, acc.w);
    }
    float4 bb = ((const float4*)b1)[tid];
    acc.x = fmaxf(acc.x + bb.x, 0.f);
    acc.y = fmaxf(acc.y + bb.y, 0.f);
    acc.z = fmaxf(acc.z + bb.z, 0.f);
    acc.w = fmaxf(acc.w + bb.w, 0.f);
    ((float4*)(g_h1 + (size_t)n * DD))[tid] = acc;
}

__global__ __launch_bounds__(128) void agg2_kernel(const float* __restrict__ b2,
                                                   float* __restrict__ out) {
    int n = blockIdx.x;
    int tid = threadIdx.x;
    int o = g_off[n];
    int cnt = g_off[n + 1] - o;

    __shared__ int   ssrc[128];
    __shared__ float sal[128];

    float4 acc = make_float4(0.f, 0.f, 0.f, 0.f);
    for (int base = 0; base < cnt; base += 128) {
        int m = min(128, cnt - base);
        if (tid < m) {
            ssrc[tid] = g_esrc[o + base + tid];
            sal[tid] = g_alpha2[o + base + tid];
        }
        __syncthreads();
        for (int j = 0; j < m; j++) {
            float a = sal[j];
            const float4* r = (const float4*)(g_g2 + (size_t)ssrc[j] * DD);
            float4 v = r[tid];
            acc.x = fmaf(a, v.x, acc.x);
            acc.y = fmaf(a, v.y, acc.y);
            acc.z = fmaf(a, v.z, acc.z);
            acc.w = fmaf(a, v.w, acc.w);
        }
        __syncthreads();
    }
    {
        float a = g_salpha2[n];
        float4 v = ((const float4*)(g_g2 + (size_t)n * DD))[tid];
        acc.x = fmaf(a, v.x, acc.x);
        acc.y = fmaf(a, v.y, acc.y);
        acc.z = fmaf(a, v.z, acc.z);
        acc.w = fmaf(a, v.w, acc.w);
    }
    float4 bb = ((const float4*)b2)[tid];
    acc.x = fmaxf(acc.x + bb.x, 0.f);
    acc.y = fmaxf(acc.y + bb.y, 0.f);
    acc.z = fmaxf(acc.z + bb.z, 0.f);
    acc.w = fmaxf(acc.w + bb.w, 0.f);
    ((float4*)(out + (size_t)n * DD))[tid] = acc;
}

// ---------------- launcher ----------------
static float* sym_f(const void* sym) {
    void* p = nullptr;
    cudaGetSymbolAddress(&p, sym);
    return (float*)p;
}

extern "C" void kernel_launch(void* const* d_in, const int* in_sizes, int n_in,
                              void* d_out, int out_size) {
    const float* x      = (const float*)d_in[0];
    const int*   adj    = (const int*)d_in[1];   // JAX int64 silently downgraded to int32
    const float* W_fc   = (const float*)d_in[2];
    const float* b_fc   = (const float*)d_in[3];
    const float* W1     = (const float*)d_in[4];
    const float* a1_src = (const float*)d_in[5];
    const float* a1_dst = (const float*)d_in[6];
    const float* b1     = (const float*)d_in[7];
    const float* W2     = (const float*)d_in[8];
    const float* a2_src = (const float*)d_in[9];
    const float* a2_dst = (const float*)d_in[10];
    const float* b2     = (const float*)d_in[11];
    float* out = (float*)d_out;

    float* p_h0 = sym_f(g_h0);
    float* p_g1 = sym_f(g_g1);
    float* p_h1 = sym_f(g_h1);
    float* p_g2 = sym_f(g_g2);

    // CSR build
    zero_kernel<<<(NN + 255) / 256, 256>>>();
    count_kernel<<<(EE + 255) / 256, 256>>>(adj);
    scan_kernel<<<1, 256>>>();
    scatter_kernel<<<(EE + 255) / 256, 256>>>(adj);

    // fc + relu: h0 = relu(x @ W_fc + b_fc)   [16384,256]
    {
        dim3 grid(H1C / 128, NN / 128);
        sgemm_kernel<true, true><<<grid, 256>>>(x, W_fc, b_fc, p_h0, NN, H1C, H1C);
    }
    // gat1 linear: g1 = h0 @ W1    [16384,512]
    {
        dim3 grid(DD / 128, NN / 128);
        sgemm_kernel<false, false><<<grid, 256>>>(p_h0, W1, nullptr, p_g1, NN, DD, H1C);
    }
    al1_kernel<<<(NN * 32 + 255) / 256, 256>>>(a1_src, a1_dst);
    alpha1_kernel<<<(NN * 32 + 255) / 256, 256>>>();
    agg1_kernel<<<NN, 128>>>(b1);

    // gat2 linear: g2 = h1 @ W2    [16384,512]
    {
        dim3 grid(DD / 128, NN / 128);
        sgemm_kernel<false, false><<<grid, 256>>>(p_h1, W2, nullptr, p_g2, NN, DD, DD);
    }
    al2_kernel<<<(NN * 32 + 255) / 256, 256>>>(a2_src, a2_dst);
    alpha2_kernel<<<(NN * 32 + 255) / 256, 256>>>();
    agg2_kernel<<<NN, 128>>>(b2, out);
}

// round 3
// speedup vs baseline: 1.8859x; 1.8859x over previous
#include <cuda_runtime.h>
#include <cuda_bf16.h>
#include <cstdint>

// Problem constants (fixed shapes per reference)
#define NN 16384      // nodes
#define EE 262144     // edges (before self loops)
#define H1C 256       // hidden_dim1
#define DD 512        // 2*H1 = D_IN = gat2 channels
#define NEG_SLOPE 0.2f

// ---------------- device scratch (no allocations allowed) ----------------
__device__ float g_h0[NN * H1C];          // relu(x@W_fc+b_fc)      16 MB
__device__ float g_g1[(size_t)NN * DD];   // h0@W1 (pre-aggregate)  32 MB
__device__ float g_h1[(size_t)NN * DD];   // relu(gat1 out)         32 MB
__device__ float g_g2[(size_t)NN * DD];   // h1@W2                  32 MB
__device__ float g_al1[NN * 4];           // per node: s0,s1,d0,d1
__device__ float g_al2[NN * 2];           // per node: s,d
__device__ int   g_deg[NN];
__device__ int   g_cursor[NN];
__device__ int   g_off[NN + 1];
__device__ int   g_esrc[EE];
__device__ float g_alpha1[(size_t)EE * 2];
__device__ float g_salpha1[NN * 2];
__device__ float g_alpha2[EE];
__device__ float g_salpha2[NN];

// ---------------- CSR construction ----------------
__global__ void zero_kernel() {
    int i = blockIdx.x * blockDim.x + threadIdx.x;
    if (i < NN) { g_deg[i] = 0; g_cursor[i] = 0; }
}

__global__ void count_kernel(const int* __restrict__ adj) {
    int i = blockIdx.x * blockDim.x + threadIdx.x;
    if (i < EE) {
        int dst = adj[EE + i];
        atomicAdd(&g_deg[dst], 1);
    }
}

// exclusive scan of g_deg (16384) -> g_off; single block of 256 threads, 64 each
__global__ void scan_kernel() {
    int t = threadIdx.x;
    int base_i = t * 64;
    int sum = 0;
    #pragma unroll 4
    for (int k = 0; k < 64; k++) sum += g_deg[base_i + k];
    __shared__ int part[256];
    part[t] = sum;
    __syncthreads();
    for (int s = 1; s < 256; s <<= 1) {
        int v = (t >= s) ? part[t - s] : 0;
        __syncthreads();
        part[t] += v;
        __syncthreads();
    }
    int run = (t > 0) ? part[t - 1] : 0;
    for (int k = 0; k < 64; k++) {
        g_off[base_i + k] = run;
        run += g_deg[base_i + k];
    }
    if (t == 255) g_off[NN] = run;
}

__global__ void scatter_kernel(const int* __restrict__ adj) {
    int i = blockIdx.x * blockDim.x + threadIdx.x;
    if (i < EE) {
        int src = adj[i];
        int dst = adj[EE + i];
        int p = g_off[dst] + atomicAdd(&g_cursor[dst], 1);
        g_esrc[p] = src;
    }
}

// ================= Tensor-core GEMM (bf16x3 split, m16n8k16) =================
// C = act(A[M,K] @ B[K,N] (+bias)).  Block tile 128x128, BK=16, 256 threads.
// fp32 inputs are split x = hi + lo (both bf16); product via 3 bf16 MMAs
// (hi*hi + hi*lo + lo*hi) accumulated in fp32 -> ~1e-5 relative error.
//
// SMEM layout per tile (A or B): word index = outer*16 + 2*(kw ^ p(outer)) + h
//   outer = m row (A) or n col (B), kw = 0..7 (k-pair index), h: 0=hi,1=lo
//   p(outer) = (((outer>>2)&1)<<2) | ((outer>>3)&3)   (XOR swizzle)
// Fragment loads are LDS.64 (hi+lo together), conflict-free.

__device__ __forceinline__ int swz(int outer, int kw) {
    int p = (((outer >> 2) & 1) << 2) | ((outer >> 3) & 3);
    return outer * 16 + 2 * (kw ^ p);
}

__device__ __forceinline__ void split_pack(float x0, float x1,
                                           uint32_t& hi, uint32_t& lo) {
    __nv_bfloat16 h0 = __float2bfloat16_rn(x0);
    __nv_bfloat16 h1 = __float2bfloat16_rn(x1);
    hi = (uint32_t)__bfloat16_as_ushort(h0) |
         ((uint32_t)__bfloat16_as_ushort(h1) << 16);
    float l0 = x0 - __bfloat162float(h0);
    float l1 = x1 - __bfloat162float(h1);
    __nv_bfloat162 lp = __floats2bfloat162_rn(l0, l1);
    lo = *reinterpret_cast<const uint32_t*>(&lp);
}

__device__ __forceinline__ void mma16816(float* d, const uint32_t* a,
                                         const uint32_t* b) {
    asm volatile(
        "mma.sync.aligned.m16n8k16.row.col.f32.bf16.bf16.f32 "
        "{%0,%1,%2,%3}, {%4,%5,%6,%7}, {%8,%9}, {%0,%1,%2,%3};\n"
        : "+f"(d[0]), "+f"(d[1]), "+f"(d[2]), "+f"(d[3])
        : "r"(a[0]), "r"(a[1]), "r"(a[2]), "r"(a[3]),
          "r"(b[0]), "r"(b[1]));
}

__device__ __forceinline__ void ldg_stage(
    const float* __restrict__ A, const float* __restrict__ B,
    int brow, int bcol, int K, int N, int k0, int tid,
    uint32_t* stA, uint32_t* stB)
{
    // A tile: 128 rows x 16 k; thread loads 2 float4 (rows tid>>2, tid>>2+64)
    #pragma unroll
    for (int f = 0; f < 2; f++) {
        const float4 v = *(const float4*)(
            A + (size_t)(brow + (tid >> 2) + 64 * f) * K + k0 + 4 * (tid & 3));
        split_pack(v.x, v.y, stA[f * 4 + 0], stA[f * 4 + 1]);
        split_pack(v.z, v.w, stA[f * 4 + 2], stA[f * 4 + 3]);
    }
    // B tile: 16 k x 128 n; thread handles k-pair kw = tid>>5, n group 4*(tid&31)
    {
        const float* bp = B + (size_t)(k0 + 2 * (tid >> 5)) * N + bcol + 4 * (tid & 31);
        float4 r0 = *(const float4*)bp;
        float4 r1 = *(const float4*)(bp + N);
        split_pack(r0.x, r1.x, stB[0], stB[1]);
        split_pack(r0.y, r1.y, stB[2], stB[3]);
        split_pack(r0.z, r1.z, stB[4], stB[5]);
        split_pack(r0.w, r1.w, stB[6], stB[7]);
    }
}

__device__ __forceinline__ void sts_stage(uint32_t* __restrict__ buf, int tid,
                                          const uint32_t* stA,
                                          const uint32_t* stB)
{
    uint32_t* Abuf = buf;
    uint32_t* Bbuf = buf + 2048;
    #pragma unroll
    for (int f = 0; f < 2; f++) {
        int row = (tid >> 2) + 64 * f;
        int c4 = tid & 3;
        *(uint2*)&Abuf[swz(row, 2 * c4)]     = make_uint2(stA[f * 4 + 0], stA[f * 4 + 1]);
        *(uint2*)&Abuf[swz(row, 2 * c4 + 1)] = make_uint2(stA[f * 4 + 2], stA[f * 4 + 3]);
    }
    {
        int kw = tid >> 5;
        int n0 = 4 * (tid & 31);
        #pragma unroll
        for (int j = 0; j < 4; j++)
            *(uint2*)&Bbuf[swz(n0 + j, kw)] = make_uint2(stB[j * 2], stB[j * 2 + 1]);
    }
}

template <bool RELU, bool HAS_BIAS>
__global__ __launch_bounds__(256, 2) void tgemm_kernel(
    const float* __restrict__ A, const float* __restrict__ B,
    const float* __restrict__ bias, float* __restrict__ C,
    int M, int N, int K)
{
    __shared__ uint32_t sm[2 * 4096];   // 2 buffers x (A 2048 + B 2048) words

    const int tid  = threadIdx.x;
    const int lane = tid & 31;
    const int wid  = tid >> 5;
    const int wm   = wid & 1;           // 2 warps along M (64 rows each)
    const int wn   = wid >> 1;          // 4 warps along N (32 cols each)
    const int brow = blockIdx.y * 128;
    const int bcol = blockIdx.x * 128;

    float acc[4][4][4];
    #pragma unroll
    for (int i = 0; i < 4; i++)
        #pragma unroll
        for (int j = 0; j < 4; j++)
            #pragma unroll
            for (int q = 0; q < 4; q++) acc[i][j][q] = 0.f;

    uint32_t stA[8], stB[8];
    const int iters = K >> 4;

    ldg_stage(A, B, brow, bcol, K, N, 0, tid, stA, stB);
    sts_stage(sm, tid, stA, stB);
    __syncthreads();

    const int c  = lane & 3;
    const int r4 = lane >> 2;

    for (int it = 0; it < iters; ++it) {
        if (it + 1 < iters)
            ldg_stage(A, B, brow, bcol, K, N, (it + 1) << 4, tid, stA, stB);

        uint32_t* buf  = sm + (it & 1) * 4096;
        uint32_t* Abuf = buf;
        uint32_t* Bbuf = buf + 2048;

        uint2 bfr[4][2];
        #pragma unroll
        for (int ni = 0; ni < 4; ni++) {
            int n0 = wn * 32 + ni * 8 + r4;
            bfr[ni][0] = *(const uint2*)&Bbuf[swz(n0, c)];
            bfr[ni][1] = *(const uint2*)&Bbuf[swz(n0, c + 4)];
        }
        #pragma unroll
        for (int mi = 0; mi < 4; mi++) {
            int m0 = wm * 64 + mi * 16 + r4;
            uint2 a0 = *(const uint2*)&Abuf[swz(m0, c)];
            uint2 a1 = *(const uint2*)&Abuf[swz(m0 + 8, c)];
            uint2 a2 = *(const uint2*)&Abuf[swz(m0, c + 4)];
            uint2 a3 = *(const uint2*)&Abuf[swz(m0 + 8, c + 4)];
            uint32_t ah[4] = {a0.x, a1.x, a2.x, a3.x};
            uint32_t al[4] = {a0.y, a1.y, a2.y, a3.y};
            #pragma unroll
            for (int ni = 0; ni < 4; ni++) {
                uint32_t bh[2] = {bfr[ni][0].x, bfr[ni][1].x};
                uint32_t bl[2] = {bfr[ni][0].y, bfr[ni][1].y};
                mma16816(acc[mi][ni], ah, bh);   // hi*hi
                mma16816(acc[mi][ni], ah, bl);   // hi*lo
                mma16816(acc[mi][ni], al, bh);   // lo*hi
            }
        }

        if (it + 1 < iters) {
            __syncthreads();
            sts_stage(sm + ((it + 1) & 1) * 4096, tid, stA, stB);
            __syncthreads();
        }
    }

    // epilogue
    #pragma unroll
    for (int mi = 0; mi < 4; mi++) {
        int row = brow + wm * 64 + mi * 16 + r4;
        #pragma unroll
        for (int ni = 0; ni < 4; ni++) {
            int col = bcol + wn * 32 + ni * 8 + 2 * c;
            float2 v0 = make_float2(acc[mi][ni][0], acc[mi][ni][1]);
            float2 v1 = make_float2(acc[mi][ni][2], acc[mi][ni][3]);
            if (HAS_BIAS) {
                float2 bb = *(const float2*)(bias + col);
                v0.x += bb.x; v0.y += bb.y;
                v1.x += bb.x; v1.y += bb.y;
            }
            if (RELU) {
                v0.x = fmaxf(v0.x, 0.f); v0.y = fmaxf(v0.y, 0.f);
                v1.x = fmaxf(v1.x, 0.f); v1.y = fmaxf(v1.y, 0.f);
            }
            *(float2*)(C + (size_t)row * N + col)       = v0;
            *(float2*)(C + (size_t)(row + 8) * N + col) = v1;
        }
    }
}

// ---------------- attention scalars ----------------
__global__ void al1_kernel(const float* __restrict__ a_src,
                           const float* __restrict__ a_dst)
{
    int gw = (blockIdx.x * blockDim.x + threadIdx.x) >> 5;
    if (gw >= NN) return;
    int lane = threadIdx.x & 31;
    const float4* row = (const float4*)(g_g1 + (size_t)gw * DD);
    const float4* as4 = (const float4*)a_src;
    const float4* ad4 = (const float4*)a_dst;
    float s0 = 0.f, s1 = 0.f, d0 = 0.f, d1 = 0.f;
    for (int c = lane; c < 128; c += 32) {
        float4 v = row[c];
        float4 a = as4[c];
        float4 b = ad4[c];
        float sv = v.x * a.x + v.y * a.y + v.z * a.z + v.w * a.w;
        float dv = v.x * b.x + v.y * b.y + v.z * b.z + v.w * b.w;
        if (c < 64) { s0 += sv; d0 += dv; } else { s1 += sv; d1 += dv; }
    }
    #pragma unroll
    for (int o = 16; o; o >>= 1) {
        s0 += __shfl_down_sync(0xffffffffu, s0, o);
        s1 += __shfl_down_sync(0xffffffffu, s1, o);
        d0 += __shfl_down_sync(0xffffffffu, d0, o);
        d1 += __shfl_down_sync(0xffffffffu, d1, o);
    }
    if (lane == 0) {
        g_al1[gw * 4 + 0] = s0;
        g_al1[gw * 4 + 1] = s1;
        g_al1[gw * 4 + 2] = d0;
        g_al1[gw * 4 + 3] = d1;
    }
}

__global__ void al2_kernel(const float* __restrict__ a_src,
                           const float* __restrict__ a_dst)
{
    int gw = (blockIdx.x * blockDim.x + threadIdx.x) >> 5;
    if (gw >= NN) return;
    int lane = threadIdx.x & 31;
    const float4* row = (const float4*)(g_g2 + (size_t)gw * DD);
    const float4* as4 = (const float4*)a_src;
    const float4* ad4 = (const float4*)a_dst;
    float s = 0.f, d = 0.f;
    for (int c = lane; c < 128; c += 32) {
        float4 v = row[c];
        float4 a = as4[c];
        float4 b = ad4[c];
        s += v.x * a.x + v.y * a.y + v.z * a.z + v.w * a.w;
        d += v.x * b.x + v.y * b.y + v.z * b.z + v.w * b.w;
    }
    #pragma unroll
    for (int o = 16; o; o >>= 1) {
        s += __shfl_down_sync(0xffffffffu, s, o);
        d += __shfl_down_sync(0xffffffffu, d, o);
    }
    if (lane == 0) {
        g_al2[gw * 2 + 0] = s;
        g_al2[gw * 2 + 1] = d;
    }
}

__device__ __forceinline__ float lrelu(float x) {
    return x > 0.f ? x : NEG_SLOPE * x;
}

// ---------------- edge softmax (warp per node, incl. self loop) ----------------
__global__ void alpha1_kernel() {
    int n = (blockIdx.x * blockDim.x + threadIdx.x) >> 5;
    if (n >= NN) return;
    int lane = threadIdx.x & 31;
    int o = g_off[n];
    int cnt = g_off[n + 1] - o;
    float dd0 = g_al1[n * 4 + 2];
    float dd1 = g_al1[n * 4 + 3];

    float m0 = -1e30f, m1 = -1e30f;
    for (int i = lane; i <= cnt; i += 32) {
        int s = (i < cnt) ? g_esrc[o + i] : n;
        float e0 = lrelu(g_al1[s * 4 + 0] + dd0);
        float e1 = lrelu(g_al1[s * 4 + 1] + dd1);
        m0 = fmaxf(m0, e0);
        m1 = fmaxf(m1, e1);
    }
    #pragma unroll
    for (int x = 16; x; x >>= 1) {
        m0 = fmaxf(m0, __shfl_xor_sync(0xffffffffu, m0, x));
        m1 = fmaxf(m1, __shfl_xor_sync(0xffffffffu, m1, x));
    }
    float sum0 = 0.f, sum1 = 0.f;
    for (int i = lane; i <= cnt; i += 32) {
        int s = (i < cnt) ? g_esrc[o + i] : n;
        sum0 += expf(lrelu(g_al1[s * 4 + 0] + dd0) - m0);
        sum1 += expf(lrelu(g_al1[s * 4 + 1] + dd1) - m1);
    }
    #pragma unroll
    for (int x = 16; x; x >>= 1) {
        sum0 += __shfl_xor_sync(0xffffffffu, sum0, x);
        sum1 += __shfl_xor_sync(0xffffffffu, sum1, x);
    }
    float inv0 = 1.f / (sum0 + 1e-16f);
    float inv1 = 1.f / (sum1 + 1e-16f);
    for (int i = lane; i <= cnt; i += 32) {
        int s = (i < cnt) ? g_esrc[o + i] : n;
        float a0 = expf(lrelu(g_al1[s * 4 + 0] + dd0) - m0) * inv0;
        float a1 = expf(lrelu(g_al1[s * 4 + 1] + dd1) - m1) * inv1;
        if (i < cnt) {
            g_alpha1[(size_t)(o + i) * 2 + 0] = a0;
            g_alpha1[(size_t)(o + i) * 2 + 1] = a1;
        } else {
            g_salpha1[n * 2 + 0] = a0;
            g_salpha1[n * 2 + 1] = a1;
        }
    }
}

__global__ void alpha2_kernel() {
    int n = (blockIdx.x * blockDim.x + threadIdx.x) >> 5;
    if (n >= NN) return;
    int lane = threadIdx.x & 31;
    int o = g_off[n];
    int cnt = g_off[n + 1] - o;
    float dd = g_al2[n * 2 + 1];

    float m = -1e30f;
    for (int i = lane; i <= cnt; i += 32) {
        int s = (i < cnt) ? g_esrc[o + i] : n;
        m = fmaxf(m, lrelu(g_al2[s * 2] + dd));
    }
    #pragma unroll
    for (int x = 16; x; x >>= 1)
        m = fmaxf(m, __shfl_xor_sync(0xffffffffu, m, x));
    float sum = 0.f;
    for (int i = lane; i <= cnt; i += 32) {
        int s = (i < cnt) ? g_esrc[o + i] : n;
        sum += expf(lrelu(g_al2[s * 2] + dd) - m);
    }
    #pragma unroll
    for (int x = 16; x; x >>= 1)
        sum += __shfl_xor_sync(0xffffffffu, sum, x);
    float inv = 1.f / (sum + 1e-16f);
    for (int i = lane; i <= cnt; i += 32) {
        int s = (i < cnt) ? g_esrc[o + i] : n;
        float a = expf(lrelu(g_al2[s * 2] + dd) - m) * inv;
        if (i < cnt) g_alpha2[o + i] = a;
        else g_salpha2[n] = a;
    }
}

// ---------------- aggregation (block of 128 threads per node) ----------------
__global__ __launch_bounds__(128) void agg1_kernel(const float* __restrict__ b1) {
    int n = blockIdx.x;
    int tid = threadIdx.x;             // 0..127, float4 column
    int o = g_off[n];
    int cnt = g_off[n + 1] - o;
    int head = tid >> 6;               // tid<64 -> head0

    __shared__ int   ssrc[128];
    __shared__ float sal[128 * 2];

    float4 acc = make_float4(0.f, 0.f, 0.f, 0.f);
    for (int base = 0; base < cnt; base += 128) {
        int m = min(128, cnt - base);
        if (tid < m) {
            ssrc[tid] = g_esrc[o + base + tid];
            sal[tid * 2 + 0] = g_alpha1[(size_t)(o + base + tid) * 2 + 0];
            sal[tid * 2 + 1] = g_alpha1[(size_t)(o + base + tid) * 2 + 1];
        }
        __syncthreads();
        for (int j = 0; j < m; j++) {
            float a = sal[j * 2 + head];
            const float4* r = (const float4*)(g_g1 + (size_t)ssrc[j] * DD);
            float4 v = r[tid];
            acc.x = fmaf(a, v.x, acc.x);
            acc.y = fmaf(a, v.y, acc.y);
            acc.z = fmaf(a, v.z, acc.z);
            acc.w = fmaf(a, v.w, acc.w);
        }
        __syncthreads();
    }
    {
        float a = g_salpha1[n * 2 + head];
        float4 v = ((const float4*)(g_g1 + (size_t)n * DD))[tid];
        acc.x = fmaf(a, v.x, acc.x);
        acc.y = fmaf(a, v.y, acc.y);
        acc.z = fmaf(a, v.z, acc.z);
        acc.w = fmaf(a, v.w, acc.w);
    }
    float4 bb = ((const float4*)b1)[tid];
    acc.x = fmaxf(acc.x + bb.x, 0.f);
    acc.y = fmaxf(acc.y + bb.y, 0.f);
    acc.z = fmaxf(acc.z + bb.z, 0.f);
    acc.w = fmaxf(acc.w + bb.w, 0.f);
    ((float4*)(g_h1 + (size_t)n * DD))[tid] = acc;
}

__global__ __launch_bounds__(128) void agg2_kernel(const float* __restrict__ b2,
                                                   float* __restrict__ out) {
    int n = blockIdx.x;
    int tid = threadIdx.x;
    int o = g_off[n];
    int cnt = g_off[n + 1] - o;

    __shared__ int   ssrc[128];
    __shared__ float sal[128];

    float4 acc = make_float4(0.f, 0.f, 0.f, 0.f);
    for (int base = 0; base < cnt; base += 128) {
        int m = min(128, cnt - base);
        if (tid < m) {
            ssrc[tid] = g_esrc[o + base + tid];
            sal[tid] = g_alpha2[o + base + tid];
        }
        __syncthreads();
        for (int j = 0; j < m; j++) {
            float a = sal[j];
            const float4* r = (const float4*)(g_g2 + (size_t)ssrc[j] * DD);
            float4 v = r[tid];
            acc.x = fmaf(a, v.x, acc.x);
            acc.y = fmaf(a, v.y, acc.y);
            acc.z = fmaf(a, v.z, acc.z);
            acc.w = fmaf(a, v.w, acc.w);
        }
        __syncthreads();
    }
    {
        float a = g_salpha2[n];
        float4 v = ((const float4*)(g_g2 + (size_t)n * DD))[tid];
        acc.x = fmaf(a, v.x, acc.x);
        acc.y = fmaf(a, v.y, acc.y);
        acc.z = fmaf(a, v.z, acc.z);
        acc.w = fmaf(a, v.w, acc.w);
    }
    float4 bb = ((const float4*)b2)[tid];
    acc.x = fmaxf(acc.x + bb.x, 0.f);
    acc.y = fmaxf(acc.y + bb.y, 0.f);
    acc.z = fmaxf(acc.z + bb.z, 0.f);
    acc.w = fmaxf(acc.w + bb.w, 0.f);
    ((float4*)(out + (size_t)n * DD))[tid] = acc;
}

// ---------------- launcher ----------------
static float* sym_f(const void* sym) {
    void* p = nullptr;
    cudaGetSymbolAddress(&p, sym);
    return (float*)p;
}

extern "C" void kernel_launch(void* const* d_in, const int* in_sizes, int n_in,
                              void* d_out, int out_size) {
    const float* x      = (const float*)d_in[0];
    const int*   adj    = (const int*)d_in[1];   // JAX x64-disabled: int32
    const float* W_fc   = (const float*)d_in[2];
    const float* b_fc   = (const float*)d_in[3];
    const float* W1     = (const float*)d_in[4];
    const float* a1_src = (const float*)d_in[5];
    const float* a1_dst = (const float*)d_in[6];
    const float* b1     = (const float*)d_in[7];
    const float* W2     = (const float*)d_in[8];
    const float* a2_src = (const float*)d_in[9];
    const float* a2_dst = (const float*)d_in[10];
    const float* b2     = (const float*)d_in[11];
    float* out = (float*)d_out;

    float* p_h0 = sym_f(g_h0);
    float* p_g1 = sym_f(g_g1);
    float* p_h1 = sym_f(g_h1);
    float* p_g2 = sym_f(g_g2);

    // CSR build
    zero_kernel<<<(NN + 255) / 256, 256>>>();
    count_kernel<<<(EE + 255) / 256, 256>>>(adj);
    scan_kernel<<<1, 256>>>();
    scatter_kernel<<<(EE + 255) / 256, 256>>>(adj);

    // fc + relu: h0 = relu(x @ W_fc + b_fc)   [16384,256]
    {
        dim3 grid(H1C / 128, NN / 128);
        tgemm_kernel<true, true><<<grid, 256>>>(x, W_fc, b_fc, p_h0, NN, H1C, H1C);
    }
    // gat1 linear: g1 = h0 @ W1    [16384,512]
    {
        dim3 grid(DD / 128, NN / 128);
        tgemm_kernel<false, false><<<grid, 256>>>(p_h0, W1, nullptr, p_g1, NN, DD, H1C);
    }
    al1_kernel<<<(NN * 32 + 255) / 256, 256>>>(a1_src, a1_dst);
    alpha1_kernel<<<(NN * 32 + 255) / 256, 256>>>();
    agg1_kernel<<<NN, 128>>>(b1);

    // gat2 linear: g2 = h1 @ W2    [16384,512]
    {
        dim3 grid(DD / 128, NN / 128);
        tgemm_kernel<false, false><<<grid, 256>>>(p_h1, W2, nullptr, p_g2, NN, DD, DD);
    }
    al2_kernel<<<(NN * 32 + 255) / 256, 256>>>(a2_src, a2_dst);
    alpha2_kernel<<<(NN * 32 + 255) / 256, 256>>>();
    agg2_kernel<<<NN, 128>>>(b2, out);
}

// round 4
// speedup vs baseline: 1.9476x; 1.0327x over previous
#include <cuda_runtime.h>
#include <cuda_bf16.h>
#include <cstdint>

// Problem constants (fixed shapes per reference)
#define NN 16384      // nodes
#define EE 262144     // edges (before self loops)
#define H1C 256       // hidden_dim1
#define DD 512        // 2*H1 = D_IN = gat2 channels
#define NEG_SLOPE 0.2f

// ---------------- device scratch (no allocations allowed) ----------------
__device__ float g_h0[NN * H1C];          // relu(x@W_fc+b_fc)      16 MB
__device__ float g_g1[(size_t)NN * DD];   // h0@W1 (pre-aggregate)  32 MB
__device__ float g_h1[(size_t)NN * DD];   // relu(gat1 out)         32 MB
__device__ float g_g2[(size_t)NN * DD];   // h1@W2                  32 MB
__device__ float g_al1[NN * 4];           // per node: s0,s1,d0,d1
__device__ float g_al2[NN * 2];           // per node: s,d
__device__ int   g_deg[NN];
__device__ int   g_cursor[NN];
__device__ int   g_off[NN + 1];
__device__ int   g_esrc[EE];
__device__ float g_alpha1[(size_t)EE * 2];
__device__ float g_salpha1[NN * 2];
__device__ float g_alpha2[EE];
__device__ float g_salpha2[NN];

// ---------------- CSR construction ----------------
__global__ void zero_kernel() {
    int i = blockIdx.x * blockDim.x + threadIdx.x;
    if (i < NN) { g_deg[i] = 0; g_cursor[i] = 0; }
}

__global__ void count_kernel(const int* __restrict__ adj) {
    int i = blockIdx.x * blockDim.x + threadIdx.x;
    if (i < EE) {
        int dst = adj[EE + i];
        atomicAdd(&g_deg[dst], 1);
    }
}

__global__ void scan_kernel() {
    int t = threadIdx.x;
    int base_i = t * 64;
    int sum = 0;
    #pragma unroll 4
    for (int k = 0; k < 64; k++) sum += g_deg[base_i + k];
    __shared__ int part[256];
    part[t] = sum;
    __syncthreads();
    for (int s = 1; s < 256; s <<= 1) {
        int v = (t >= s) ? part[t - s] : 0;
        __syncthreads();
        part[t] += v;
        __syncthreads();
    }
    int run = (t > 0) ? part[t - 1] : 0;
    for (int k = 0; k < 64; k++) {
        g_off[base_i + k] = run;
        run += g_deg[base_i + k];
    }
    if (t == 255) g_off[NN] = run;
}

__global__ void scatter_kernel(const int* __restrict__ adj) {
    int i = blockIdx.x * blockDim.x + threadIdx.x;
    if (i < EE) {
        int src = adj[i];
        int dst = adj[EE + i];
        int p = g_off[dst] + atomicAdd(&g_cursor[dst], 1);
        g_esrc[p] = src;
    }
}

// ================= Tensor-core GEMM (bf16x3 split, m16n8k16) =================
// C = act(A[M,K] @ B[K,N] (+bias)).  Block tile 128x128, BK=16, 256 threads.
// fp32 inputs split x = hi + lo (bf16 each); D += Ah*Bh + Ah*Bl + Al*Bh.
//
// Conflict-free SMEM layout (per tile, 128 outer x 8 kw, hi/lo interleaved):
//   line     = outer >> 1                       (two outers per 128B line)
//   logchunk = (outer&1)*4 + (kw>>1)            (8 x 16B chunks per line)
//   M(line)  = ((line&3)<<1) | ((line>>2)&1)    (3-bit XOR mask)
//   word     = line*32 + 4*(logchunk ^ M) + 2*(kw&1) + {0=hi,1=lo}
// Verified conflict-free for: frag LDS.64 (A & B, both kw halves),
// A STS.128 (row=tid>>2 staging), B STS.128 (chunk-per-thread staging).

__device__ __forceinline__ int smw(int outer, int kw) {
    int line = outer >> 1;
    int M = ((line & 3) << 1) | ((line >> 2) & 1);
    int lc = ((outer & 1) << 2) + (kw >> 1);
    return line * 32 + (((lc ^ M) << 2) | ((kw & 1) << 1));
}

__device__ __forceinline__ void split_pack(float x0, float x1,
                                           uint32_t& hi, uint32_t& lo) {
    __nv_bfloat16 h0 = __float2bfloat16_rn(x0);
    __nv_bfloat16 h1 = __float2bfloat16_rn(x1);
    hi = (uint32_t)__bfloat16_as_ushort(h0) |
         ((uint32_t)__bfloat16_as_ushort(h1) << 16);
    float l0 = x0 - __bfloat162float(h0);
    float l1 = x1 - __bfloat162float(h1);
    __nv_bfloat162 lp = __floats2bfloat162_rn(l0, l1);
    lo = *reinterpret_cast<const uint32_t*>(&lp);
}

__device__ __forceinline__ void mma16816(float* d, const uint32_t* a,
                                         const uint32_t* b) {
    asm volatile(
        "mma.sync.aligned.m16n8k16.row.col.f32.bf16.bf16.f32 "
        "{%0,%1,%2,%3}, {%4,%5,%6,%7}, {%8,%9}, {%0,%1,%2,%3};\n"
        : "+f"(d[0]), "+f"(d[1]), "+f"(d[2]), "+f"(d[3])
        : "r"(a[0]), "r"(a[1]), "r"(a[2]), "r"(a[3]),
          "r"(b[0]), "r"(b[1]));
}

// Register staging: A = 2 chunks (uint4), B = 2 chunks (uint4)
__device__ __forceinline__ void ldg_stage(
    const float* __restrict__ A, const float* __restrict__ B,
    int brow, int bcol, int K, int N, int k0, int tid,
    uint4* stA, uint4* stB)
{
    // A: thread -> rows (tid>>2) and (tid>>2)+64, k-chunk c4=tid&3 (4 floats)
    #pragma unroll
    for (int f = 0; f < 2; f++) {
        const float4 v = *(const float4*)(
            A + (size_t)(brow + (tid >> 2) + 64 * f) * K + k0 + 4 * (tid & 3));
        split_pack(v.x, v.y, stA[f].x, stA[f].y);
        split_pack(v.z, v.w, stA[f].z, stA[f].w);
    }
    // B: thread -> k-chunk tc=tid>>6 (4 k rows), n = 2m, 2m+1 (m = tid&63)
    {
        int tc = tid >> 6;
        int m  = tid & 63;
        const float* bp = B + (size_t)(k0 + 4 * tc) * N + bcol + 2 * m;
        float2 r0 = *(const float2*)bp;
        float2 r1 = *(const float2*)(bp + N);
        float2 r2 = *(const float2*)(bp + 2 * N);
        float2 r3 = *(const float2*)(bp + 3 * N);
        split_pack(r0.x, r1.x, stB[0].x, stB[0].y);   // n=2m,  kw=2tc
        split_pack(r2.x, r3.x, stB[0].z, stB[0].w);   // n=2m,  kw=2tc+1
        split_pack(r0.y, r1.y, stB[1].x, stB[1].y);   // n=2m+1
        split_pack(r2.y, r3.y, stB[1].z, stB[1].w);
    }
}

__device__ __forceinline__ void sts_stage(uint32_t* __restrict__ buf, int tid,
                                          const uint4* stA, const uint4* stB)
{
    uint32_t* Abuf = buf;
    uint32_t* Bbuf = buf + 2048;
    int c4 = tid & 3;
    #pragma unroll
    for (int f = 0; f < 2; f++) {
        int row = (tid >> 2) + 64 * f;
        *(uint4*)&Abuf[smw(row, 2 * c4)] = stA[f];
    }
    {
        int tc = tid >> 6;
        int m  = tid & 63;
        *(uint4*)&Bbuf[smw(2 * m,     2 * tc)] = stB[0];
        *(uint4*)&Bbuf[smw(2 * m + 1, 2 * tc)] = stB[1];
    }
}

template <bool RELU, bool HAS_BIAS>
__global__ __launch_bounds__(256, 2) void tgemm_kernel(
    const float* __restrict__ A, const float* __restrict__ B,
    const float* __restrict__ bias, float* __restrict__ C,
    int M, int N, int K)
{
    __shared__ uint32_t sm[2 * 4096];   // 2 buffers x (A 2048 + B 2048) words

    const int tid  = threadIdx.x;
    const int lane = tid & 31;
    const int wid  = tid >> 5;
    const int wm   = wid & 1;           // 2 warps along M (64 rows each)
    const int wn   = wid >> 1;          // 4 warps along N (32 cols each)
    const int brow = blockIdx.y * 128;
    const int bcol = blockIdx.x * 128;

    float acc[4][4][4];
    #pragma unroll
    for (int i = 0; i < 4; i++)
        #pragma unroll
        for (int j = 0; j < 4; j++)
            #pragma unroll
            for (int q = 0; q < 4; q++) acc[i][j][q] = 0.f;

    uint4 stA[2], stB[2];
    const int iters = K >> 4;

    ldg_stage(A, B, brow, bcol, K, N, 0, tid, stA, stB);
    sts_stage(sm, tid, stA, stB);
    __syncthreads();

    const int c  = lane & 3;
    const int r4 = lane >> 2;

    // lane-constant fragment offsets (relative; add outer*16 scaled bases)
    // A: word = (wm*64 + mi*16)*16 + smw(r4 (+8), c (+4))
    const int offA0 = smw(r4, c);
    const int offA1 = smw(8 + r4, c);
    const int offA2 = smw(r4, c + 4);
    const int offA3 = smw(8 + r4, c + 4);

    for (int it = 0; it < iters; ++it) {
        if (it + 1 < iters)
            ldg_stage(A, B, brow, bcol, K, N, (it + 1) << 4, tid, stA, stB);

        uint32_t* buf  = sm + (it & 1) * 4096;
        uint32_t* Abuf = buf;
        uint32_t* Bbuf = buf + 2048;

        uint2 bfr[4][2];
        #pragma unroll
        for (int ni = 0; ni < 4; ni++) {
            int base = wn * 512;
            bfr[ni][0] = *(const uint2*)&Bbuf[base + smw(ni * 8 + r4, c)];
            bfr[ni][1] = *(const uint2*)&Bbuf[base + smw(ni * 8 + r4, c + 4)];
        }
        #pragma unroll
        for (int mi = 0; mi < 4; mi++) {
            int base = (wm * 64 + mi * 16) * 16;
            uint2 a0 = *(const uint2*)&Abuf[base + offA0];
            uint2 a1 = *(const uint2*)&Abuf[base + offA1];
            uint2 a2 = *(const uint2*)&Abuf[base + offA2];
            uint2 a3 = *(const uint2*)&Abuf[base + offA3];
            uint32_t ah[4] = {a0.x, a1.x, a2.x, a3.x};
            uint32_t al[4] = {a0.y, a1.y, a2.y, a3.y};
            #pragma unroll
            for (int ni = 0; ni < 4; ni++) {
                uint32_t bh[2] = {bfr[ni][0].x, bfr[ni][1].x};
                uint32_t bl[2] = {bfr[ni][0].y, bfr[ni][1].y};
                mma16816(acc[mi][ni], ah, bh);   // hi*hi
                mma16816(acc[mi][ni], ah, bl);   // hi*lo
                mma16816(acc[mi][ni], al, bh);   // lo*hi
            }
        }

        if (it + 1 < iters) {
            sts_stage(sm + ((it + 1) & 1) * 4096, tid, stA, stB);
            __syncthreads();
        }
    }

    // epilogue
    #pragma unroll
    for (int mi = 0; mi < 4; mi++) {
        int row = brow + wm * 64 + mi * 16 + r4;
        #pragma unroll
        for (int ni = 0; ni < 4; ni++) {
            int col = bcol + wn * 32 + ni * 8 + 2 * c;
            float2 v0 = make_float2(acc[mi][ni][0], acc[mi][ni][1]);
            float2 v1 = make_float2(acc[mi][ni][2], acc[mi][ni][3]);
            if (HAS_BIAS) {
                float2 bb = *(const float2*)(bias + col);
                v0.x += bb.x; v0.y += bb.y;
                v1.x += bb.x; v1.y += bb.y;
            }
            if (RELU) {
                v0.x = fmaxf(v0.x, 0.f); v0.y = fmaxf(v0.y, 0.f);
                v1.x = fmaxf(v1.x, 0.f); v1.y = fmaxf(v1.y, 0.f);
            }
            *(float2*)(C + (size_t)row * N + col)       = v0;
            *(float2*)(C + (size_t)(row + 8) * N + col) = v1;
        }
    }
}

// ---------------- attention scalars ----------------
__global__ void al1_kernel(const float* __restrict__ a_src,
                           const float* __restrict__ a_dst)
{
    int gw = (blockIdx.x * blockDim.x + threadIdx.x) >> 5;
    if (gw >= NN) return;
    int lane = threadIdx.x & 31;
    const float4* row = (const float4*)(g_g1 + (size_t)gw * DD);
    const float4* as4 = (const float4*)a_src;
    const float4* ad4 = (const float4*)a_dst;
    float s0 = 0.f, s1 = 0.f, d0 = 0.f, d1 = 0.f;
    for (int c = lane; c < 128; c += 32) {
        float4 v = row[c];
        float4 a = as4[c];
        float4 b = ad4[c];
        float sv = v.x * a.x + v.y * a.y + v.z * a.z + v.w * a.w;
        float dv = v.x * b.x + v.y * b.y + v.z * b.z + v.w * b.w;
        if (c < 64) { s0 += sv; d0 += dv; } else { s1 += sv; d1 += dv; }
    }
    #pragma unroll
    for (int o = 16; o; o >>= 1) {
        s0 += __shfl_down_sync(0xffffffffu, s0, o);
        s1 += __shfl_down_sync(0xffffffffu, s1, o);
        d0 += __shfl_down_sync(0xffffffffu, d0, o);
        d1 += __shfl_down_sync(0xffffffffu, d1, o);
    }
    if (lane == 0) {
        g_al1[gw * 4 + 0] = s0;
        g_al1[gw * 4 + 1] = s1;
        g_al1[gw * 4 + 2] = d0;
        g_al1[gw * 4 + 3] = d1;
    }
}

__global__ void al2_kernel(const float* __restrict__ a_src,
                           const float* __restrict__ a_dst)
{
    int gw = (blockIdx.x * blockDim.x + threadIdx.x) >> 5;
    if (gw >= NN) return;
    int lane = threadIdx.x & 31;
    const float4* row = (const float4*)(g_g2 + (size_t)gw * DD);
    const float4* as4 = (const float4*)a_src;
    const float4* ad4 = (const float4*)a_dst;
    float s = 0.f, d = 0.f;
    for (int c = lane; c < 128; c += 32) {
        float4 v = row[c];
        float4 a = as4[c];
        float4 b = ad4[c];
        s += v.x * a.x + v.y * a.y + v.z * a.z + v.w * a.w;
        d += v.x * b.x + v.y * b.y + v.z * b.z + v.w * b.w;
    }
    #pragma unroll
    for (int o = 16; o; o >>= 1) {
        s += __shfl_down_sync(0xffffffffu, s, o);
        d += __shfl_down_sync(0xffffffffu, d, o);
    }
    if (lane == 0) {
        g_al2[gw * 2 + 0] = s;
        g_al2[gw * 2 + 1] = d;
    }
}

__device__ __forceinline__ float lrelu(float x) {
    return x > 0.f ? x : NEG_SLOPE * x;
}

// ---------------- edge softmax (warp per node, incl. self loop) ----------------
__global__ void alpha1_kernel() {
    int n = (blockIdx.x * blockDim.x + threadIdx.x) >> 5;
    if (n >= NN) return;
    int lane = threadIdx.x & 31;
    int o = g_off[n];
    int cnt = g_off[n + 1] - o;
    float dd0 = g_al1[n * 4 + 2];
    float dd1 = g_al1[n * 4 + 3];

    float m0 = -1e30f, m1 = -1e30f;
    for (int i = lane; i <= cnt; i += 32) {
        int s = (i < cnt) ? g_esrc[o + i] : n;
        float e0 = lrelu(g_al1[s * 4 + 0] + dd0);
        float e1 = lrelu(g_al1[s * 4 + 1] + dd1);
        m0 = fmaxf(m0, e0);
        m1 = fmaxf(m1, e1);
    }
    #pragma unroll
    for (int x = 16; x; x >>= 1) {
        m0 = fmaxf(m0, __shfl_xor_sync(0xffffffffu, m0, x));
        m1 = fmaxf(m1, __shfl_xor_sync(0xffffffffu, m1, x));
    }
    float sum0 = 0.f, sum1 = 0.f;
    for (int i = lane; i <= cnt; i += 32) {
        int s = (i < cnt) ? g_esrc[o + i] : n;
        sum0 += expf(lrelu(g_al1[s * 4 + 0] + dd0) - m0);
        sum1 += expf(lrelu(g_al1[s * 4 + 1] + dd1) - m1);
    }
    #pragma unroll
    for (int x = 16; x; x >>= 1) {
        sum0 += __shfl_xor_sync(0xffffffffu, sum0, x);
        sum1 += __shfl_xor_sync(0xffffffffu, sum1, x);
    }
    float inv0 = 1.f / (sum0 + 1e-16f);
    float inv1 = 1.f / (sum1 + 1e-16f);
    for (int i = lane; i <= cnt; i += 32) {
        int s = (i < cnt) ? g_esrc[o + i] : n;
        float a0 = expf(lrelu(g_al1[s * 4 + 0] + dd0) - m0) * inv0;
        float a1 = expf(lrelu(g_al1[s * 4 + 1] + dd1) - m1) * inv1;
        if (i < cnt) {
            g_alpha1[(size_t)(o + i) * 2 + 0] = a0;
            g_alpha1[(size_t)(o + i) * 2 + 1] = a1;
        } else {
            g_salpha1[n * 2 + 0] = a0;
            g_salpha1[n * 2 + 1] = a1;
        }
    }
}

__global__ void alpha2_kernel() {
    int n = (blockIdx.x * blockDim.x + threadIdx.x) >> 5;
    if (n >= NN) return;
    int lane = threadIdx.x & 31;
    int o = g_off[n];
    int cnt = g_off[n + 1] - o;
    float dd = g_al2[n * 2 + 1];

    float m = -1e30f;
    for (int i = lane; i <= cnt; i += 32) {
        int s = (i < cnt) ? g_esrc[o + i] : n;
        m = fmaxf(m, lrelu(g_al2[s * 2] + dd));
    }
    #pragma unroll
    for (int x = 16; x; x >>= 1)
        m = fmaxf(m, __shfl_xor_sync(0xffffffffu, m, x));
    float sum = 0.f;
    for (int i = lane; i <= cnt; i += 32) {
        int s = (i < cnt) ? g_esrc[o + i] : n;
        sum += expf(lrelu(g_al2[s * 2] + dd) - m);
    }
    #pragma unroll
    for (int x = 16; x; x >>= 1)
        sum += __shfl_xor_sync(0xffffffffu, sum, x);
    float inv = 1.f / (sum + 1e-16f);
    for (int i = lane; i <= cnt; i += 32) {
        int s = (i < cnt) ? g_esrc[o + i] : n;
        float a = expf(lrelu(g_al2[s * 2] + dd) - m) * inv;
        if (i < cnt) g_alpha2[o + i] = a;
        else g_salpha2[n] = a;
    }
}

// ---------------- aggregation (block of 128 threads per node) ----------------
__global__ __launch_bounds__(128) void agg1_kernel(const float* __restrict__ b1) {
    int n = blockIdx.x;
    int tid = threadIdx.x;             // 0..127, float4 column
    int o = g_off[n];
    int cnt = g_off[n + 1] - o;
    int head = tid >> 6;               // tid<64 -> head0

    __shared__ int   ssrc[128];
    __shared__ float sal[128 * 2];

    float4 acc = make_float4(0.f, 0.f, 0.f, 0.f);
    for (int base = 0; base < cnt; base += 128) {
        int m = min(128, cnt - base);
        if (tid < m) {
            ssrc[tid] = g_esrc[o + base + tid];
            sal[tid * 2 + 0] = g_alpha1[(size_t)(o + base + tid) * 2 + 0];
            sal[tid * 2 + 1] = g_alpha1[(size_t)(o + base + tid) * 2 + 1];
        }
        __syncthreads();
        for (int j = 0; j < m; j++) {
            float a = sal[j * 2 + head];
            const float4* r = (const float4*)(g_g1 + (size_t)ssrc[j] * DD);
            float4 v = r[tid];
            acc.x = fmaf(a, v.x, acc.x);
            acc.y = fmaf(a, v.y, acc.y);
            acc.z = fmaf(a, v.z, acc.z);
            acc.w = fmaf(a, v.w, acc.w);
        }
        __syncthreads();
    }
    {
        float a = g_salpha1[n * 2 + head];
        float4 v = ((const float4*)(g_g1 + (size_t)n * DD))[tid];
        acc.x = fmaf(a, v.x, acc.x);
        acc.y = fmaf(a, v.y, acc.y);
        acc.z = fmaf(a, v.z, acc.z);
        acc.w = fmaf(a, v.w, acc.w);
    }
    float4 bb = ((const float4*)b1)[tid];
    acc.x = fmaxf(acc.x + bb.x, 0.f);
    acc.y = fmaxf(acc.y + bb.y, 0.f);
    acc.z = fmaxf(acc.z + bb.z, 0.f);
    acc.w = fmaxf(acc.w + bb.w, 0.f);
    ((float4*)(g_h1 + (size_t)n * DD))[tid] = acc;
}

__global__ __launch_bounds__(128) void agg2_kernel(const float* __restrict__ b2,
                                                   float* __restrict__ out) {
    int n = blockIdx.x;
    int tid = threadIdx.x;
    int o = g_off[n];
    int cnt = g_off[n + 1] - o;

    __shared__ int   ssrc[128];
    __shared__ float sal[128];

    float4 acc = make_float4(0.f, 0.f, 0.f, 0.f);
    for (int base = 0; base < cnt; base += 128) {
        int m = min(128, cnt - base);
        if (tid < m) {
            ssrc[tid] = g_esrc[o + base + tid];
            sal[tid] = g_alpha2[o + base + tid];
        }
        __syncthreads();
        for (int j = 0; j < m; j++) {
            float a = sal[j];
            const float4* r = (const float4*)(g_g2 + (size_t)ssrc[j] * DD);
            float4 v = r[tid];
            acc.x = fmaf(a, v.x, acc.x);
            acc.y = fmaf(a, v.y, acc.y);
            acc.z = fmaf(a, v.z, acc.z);
            acc.w = fmaf(a, v.w, acc.w);
        }
        __syncthreads();
    }
    {
        float a = g_salpha2[n];
        float4 v = ((const float4*)(g_g2 + (size_t)n * DD))[tid];
        acc.x = fmaf(a, v.x, acc.x);
        acc.y = fmaf(a, v.y, acc.y);
        acc.z = fmaf(a, v.z, acc.z);
        acc.w = fmaf(a, v.w, acc.w);
    }
    float4 bb = ((const float4*)b2)[tid];
    acc.x = fmaxf(acc.x + bb.x, 0.f);
    acc.y = fmaxf(acc.y + bb.y, 0.f);
    acc.z = fmaxf(acc.z + bb.z, 0.f);
    acc.w = fmaxf(acc.w + bb.w, 0.f);
    ((float4*)(out + (size_t)n * DD))[tid] = acc;
}

// ---------------- launcher ----------------
static float* sym_f(const void* sym) {
    void* p = nullptr;
    cudaGetSymbolAddress(&p, sym);
    return (float*)p;
}

extern "C" void kernel_launch(void* const* d_in, const int* in_sizes, int n_in,
                              void* d_out, int out_size) {
    const float* x      = (const float*)d_in[0];
    const int*   adj    = (const int*)d_in[1];   // JAX x64-disabled: int32
    const float* W_fc   = (const float*)d_in[2];
    const float* b_fc   = (const float*)d_in[3];
    const float* W1     = (const float*)d_in[4];
    const float* a1_src = (const float*)d_in[5];
    const float* a1_dst = (const float*)d_in[6];
    const float* b1     = (const float*)d_in[7];
    const float* W2     = (const float*)d_in[8];
    const float* a2_src = (const float*)d_in[9];
    const float* a2_dst = (const float*)d_in[10];
    const float* b2     = (const float*)d_in[11];
    float* out = (float*)d_out;

    float* p_h0 = sym_f(g_h0);
    float* p_g1 = sym_f(g_g1);
    float* p_h1 = sym_f(g_h1);
    float* p_g2 = sym_f(g_g2);

    // CSR build
    zero_kernel<<<(NN + 255) / 256, 256>>>();
    count_kernel<<<(EE + 255) / 256, 256>>>(adj);
    scan_kernel<<<1, 256>>>();
    scatter_kernel<<<(EE + 255) / 256, 256>>>(adj);

    // fc + relu: h0 = relu(x @ W_fc + b_fc)   [16384,256]
    {
        dim3 grid(H1C / 128, NN / 128);
        tgemm_kernel<true, true><<<grid, 256>>>(x, W_fc, b_fc, p_h0, NN, H1C, H1C);
    }
    // gat1 linear: g1 = h0 @ W1    [16384,512]
    {
        dim3 grid(DD / 128, NN / 128);
        tgemm_kernel<false, false><<<grid, 256>>>(p_h0, W1, nullptr, p_g1, NN, DD, H1C);
    }
    al1_kernel<<<(NN * 32 + 255) / 256, 256>>>(a1_src, a1_dst);
    alpha1_kernel<<<(NN * 32 + 255) / 256, 256>>>();
    agg1_kernel<<<NN, 128>>>(b1);

    // gat2 linear: g2 = h1 @ W2    [16384,512]
    {
        dim3 grid(DD / 128, NN / 128);
        tgemm_kernel<false, false><<<grid, 256>>>(p_h1, W2, nullptr, p_g2, NN, DD, DD);
    }
    al2_kernel<<<(NN * 32 + 255) / 256, 256>>>(a2_src, a2_dst);
    alpha2_kernel<<<(NN * 32 + 255) / 256, 256>>>();
    agg2_kernel<<<NN, 128>>>(b2, out);
}

// round 5
// speedup vs baseline: 2.0747x; 1.0653x over previous
#include <cuda_runtime.h>
#include <cuda_bf16.h>
#include <cstdint>

// Problem constants (fixed shapes per reference)
#define NN 16384      // nodes
#define EE 262144     // edges (before self loops)
#define H1C 256       // hidden_dim1
#define DD 512        // 2*H1 = D_IN = gat2 channels
#define NEG_SLOPE 0.2f

// ---------------- device scratch (no allocations allowed) ----------------
// Packed split-bf16 activation format ("A-layout"): one uint32 word per fp32
// element; word[2i] = bf16x2(hi(e2i), hi(e2i+1)), word[2i+1] = bf16x2(lo pair).
__device__ uint32_t g_xp [NN * H1C];           // packed x            16 MB
__device__ uint32_t g_h0p[NN * H1C];           // packed relu(fc)     16 MB
__device__ uint32_t g_h1p[(size_t)NN * DD];    // packed relu(gat1)   32 MB
__device__ float    g_g1[(size_t)NN * DD];     // h0@W1 fp32          32 MB
__device__ float    g_g2[(size_t)NN * DD];     // h1@W2 fp32          32 MB
// Packed weights ("B-layout"): uint4 per (4k x 1n): {hi(k0,k1),lo(k0,k1),hi(k2,k3),lo(k2,k3)}
__device__ uint4 g_wfcp[(H1C / 4) * H1C];      // 1 MB
__device__ uint4 g_w1p [(H1C / 4) * DD];       // 2 MB
__device__ uint4 g_w2p [(DD / 4) * DD];        // 4 MB

__device__ float g_al1[NN * 4];
__device__ float g_al2[NN * 2];
__device__ int   g_deg[NN];
__device__ int   g_cursor[NN];
__device__ int   g_off[NN + 1];
__device__ int   g_esrc[EE];
__device__ float g_alpha1[(size_t)EE * 2];
__device__ float g_salpha1[NN * 2];
__device__ float g_alpha2[EE];
__device__ float g_salpha2[NN];

// ---------------- split helpers ----------------
__device__ __forceinline__ void split_pack(float x0, float x1,
                                           uint32_t& hi, uint32_t& lo) {
    __nv_bfloat16 h0 = __float2bfloat16_rn(x0);
    __nv_bfloat16 h1 = __float2bfloat16_rn(x1);
    hi = (uint32_t)__bfloat16_as_ushort(h0) |
         ((uint32_t)__bfloat16_as_ushort(h1) << 16);
    float l0 = x0 - __bfloat162float(h0);
    float l1 = x1 - __bfloat162float(h1);
    __nv_bfloat162 lp = __floats2bfloat162_rn(l0, l1);
    lo = *reinterpret_cast<const uint32_t*>(&lp);
}

// ---------------- pre-pack kernels ----------------
__global__ void pack_a_kernel(const float* __restrict__ X,
                              uint32_t* __restrict__ P, int npairs) {
    int i = blockIdx.x * blockDim.x + threadIdx.x;
    if (i < npairs) {
        float2 v = *(const float2*)(X + 2 * (size_t)i);
        split_pack(v.x, v.y, P[2 * (size_t)i], P[2 * (size_t)i + 1]);
    }
}

__global__ void pack_b_kernel(const float* __restrict__ W,
                              uint4* __restrict__ P, int K, int N) {
    int idx = blockIdx.x * blockDim.x + threadIdx.x;
    int total = (K / 4) * N;
    if (idx >= total) return;
    int c = idx / N;
    int n = idx - c * N;
    const float* wp = W + (size_t)(4 * c) * N + n;
    float w0 = wp[0], w1 = wp[N], w2 = wp[2 * N], w3 = wp[3 * N];
    uint4 o;
    split_pack(w0, w1, o.x, o.y);
    split_pack(w2, w3, o.z, o.w);
    P[idx] = o;
}

// ---------------- CSR construction ----------------
__global__ void zero_kernel() {
    int i = blockIdx.x * blockDim.x + threadIdx.x;
    if (i < NN) { g_deg[i] = 0; g_cursor[i] = 0; }
}

__global__ void count_kernel(const int* __restrict__ adj) {
    int i = blockIdx.x * blockDim.x + threadIdx.x;
    if (i < EE) atomicAdd(&g_deg[adj[EE + i]], 1);
}

__global__ void scan_kernel() {
    int t = threadIdx.x;
    int base_i = t * 64;
    int sum = 0;
    #pragma unroll 4
    for (int k = 0; k < 64; k++) sum += g_deg[base_i + k];
    __shared__ int part[256];
    part[t] = sum;
    __syncthreads();
    for (int s = 1; s < 256; s <<= 1) {
        int v = (t >= s) ? part[t - s] : 0;
        __syncthreads();
        part[t] += v;
        __syncthreads();
    }
    int run = (t > 0) ? part[t - 1] : 0;
    for (int k = 0; k < 64; k++) {
        g_off[base_i + k] = run;
        run += g_deg[base_i + k];
    }
    if (t == 255) g_off[NN] = run;
}

__global__ void scatter_kernel(const int* __restrict__ adj) {
    int i = blockIdx.x * blockDim.x + threadIdx.x;
    if (i < EE) {
        int src = adj[i];
        int dst = adj[EE + i];
        int p = g_off[dst] + atomicAdd(&g_cursor[dst], 1);
        g_esrc[p] = src;
    }
}

// ================= Tensor-core GEMM (bf16x3 split, pre-packed inputs) =========
// Conflict-free SMEM layout (verified): word = line*32 + 4*(lc^M) + 2*(kw&1)+h
__device__ __forceinline__ int smw(int outer, int kw) {
    int line = outer >> 1;
    int M = ((line & 3) << 1) | ((line >> 2) & 1);
    int lc = ((outer & 1) << 2) + (kw >> 1);
    return line * 32 + (((lc ^ M) << 2) | ((kw & 1) << 1));
}

__device__ __forceinline__ void mma16816(float* d, const uint32_t* a,
                                         const uint32_t* b) {
    asm volatile(
        "mma.sync.aligned.m16n8k16.row.col.f32.bf16.bf16.f32 "
        "{%0,%1,%2,%3}, {%4,%5,%6,%7}, {%8,%9}, {%0,%1,%2,%3};\n"
        : "+f"(d[0]), "+f"(d[1]), "+f"(d[2]), "+f"(d[3])
        : "r"(a[0]), "r"(a[1]), "r"(a[2]), "r"(a[3]),
          "r"(b[0]), "r"(b[1]));
}

__device__ __forceinline__ void ldg_stage_p(
    const uint32_t* __restrict__ Ap, const uint4* __restrict__ Bp,
    int brow, int bcol, int K, int N, int k0, int tid,
    uint4* stA, uint4* stB)
{
    #pragma unroll
    for (int f = 0; f < 2; f++)
        stA[f] = *(const uint4*)(
            Ap + (size_t)(brow + (tid >> 2) + 64 * f) * K + k0 + 4 * (tid & 3));
    int tc = tid >> 6;
    int m  = tid & 63;
    const uint4* bp = Bp + (size_t)((k0 >> 2) + tc) * N + bcol + 2 * m;
    stB[0] = bp[0];
    stB[1] = bp[1];
}

__device__ __forceinline__ void sts_stage(uint32_t* __restrict__ buf, int tid,
                                          const uint4* stA, const uint4* stB)
{
    uint32_t* Abuf = buf;
    uint32_t* Bbuf = buf + 2048;
    int c4 = tid & 3;
    #pragma unroll
    for (int f = 0; f < 2; f++)
        *(uint4*)&Abuf[smw((tid >> 2) + 64 * f, 2 * c4)] = stA[f];
    int tc = tid >> 6;
    int m  = tid & 63;
    *(uint4*)&Bbuf[smw(2 * m,     2 * tc)] = stB[0];
    *(uint4*)&Bbuf[smw(2 * m + 1, 2 * tc)] = stB[1];
}

// OUT_MODE: 0 = fp32 plain, 1 = packed split-bf16 with bias+relu
template <int OUT_MODE>
__global__ __launch_bounds__(256, 2) void tgemm_p_kernel(
    const uint32_t* __restrict__ Ap, const uint4* __restrict__ Bp,
    const float* __restrict__ bias, void* __restrict__ Cout,
    int M, int N, int K)
{
    __shared__ uint32_t sm[2 * 4096];

    const int tid  = threadIdx.x;
    const int lane = tid & 31;
    const int wid  = tid >> 5;
    const int wm   = wid & 1;
    const int wn   = wid >> 1;
    const int brow = blockIdx.y * 128;
    const int bcol = blockIdx.x * 128;

    float acc[4][4][4];
    #pragma unroll
    for (int i = 0; i < 4; i++)
        #pragma unroll
        for (int j = 0; j < 4; j++)
            #pragma unroll
            for (int q = 0; q < 4; q++) acc[i][j][q] = 0.f;

    uint4 stA[2], stB[2];
    const int iters = K >> 4;

    ldg_stage_p(Ap, Bp, brow, bcol, K, N, 0, tid, stA, stB);
    sts_stage(sm, tid, stA, stB);
    __syncthreads();

    const int c  = lane & 3;
    const int r4 = lane >> 2;

    const int offA0 = smw(r4, c);
    const int offA1 = smw(8 + r4, c);
    const int offA2 = smw(r4, c + 4);
    const int offA3 = smw(8 + r4, c + 4);

    for (int it = 0; it < iters; ++it) {
        if (it + 1 < iters)
            ldg_stage_p(Ap, Bp, brow, bcol, K, N, (it + 1) << 4, tid, stA, stB);

        uint32_t* buf  = sm + (it & 1) * 4096;
        uint32_t* Abuf = buf;
        uint32_t* Bbuf = buf + 2048;

        uint2 bfr[4][2];
        #pragma unroll
        for (int ni = 0; ni < 4; ni++) {
            int base = wn * 512;
            bfr[ni][0] = *(const uint2*)&Bbuf[base + smw(ni * 8 + r4, c)];
            bfr[ni][1] = *(const uint2*)&Bbuf[base + smw(ni * 8 + r4, c + 4)];
        }
        #pragma unroll
        for (int mi = 0; mi < 4; mi++) {
            int base = (wm * 64 + mi * 16) * 16;
            uint2 a0 = *(const uint2*)&Abuf[base + offA0];
            uint2 a1 = *(const uint2*)&Abuf[base + offA1];
            uint2 a2 = *(const uint2*)&Abuf[base + offA2];
            uint2 a3 = *(const uint2*)&Abuf[base + offA3];
            uint32_t ah[4] = {a0.x, a1.x, a2.x, a3.x};
            uint32_t al[4] = {a0.y, a1.y, a2.y, a3.y};
            #pragma unroll
            for (int ni = 0; ni < 4; ni++) {
                uint32_t bh[2] = {bfr[ni][0].x, bfr[ni][1].x};
                uint32_t bl[2] = {bfr[ni][0].y, bfr[ni][1].y};
                mma16816(acc[mi][ni], ah, bh);
                mma16816(acc[mi][ni], ah, bl);
                mma16816(acc[mi][ni], al, bh);
            }
        }

        if (it + 1 < iters) {
            sts_stage(sm + ((it + 1) & 1) * 4096, tid, stA, stB);
            __syncthreads();
        }
    }

    #pragma unroll
    for (int mi = 0; mi < 4; mi++) {
        int row = brow + wm * 64 + mi * 16 + r4;
        #pragma unroll
        for (int ni = 0; ni < 4; ni++) {
            int col = bcol + wn * 32 + ni * 8 + 2 * c;
            float2 v0 = make_float2(acc[mi][ni][0], acc[mi][ni][1]);
            float2 v1 = make_float2(acc[mi][ni][2], acc[mi][ni][3]);
            if (OUT_MODE == 1) {
                float2 bb = *(const float2*)(bias + col);
                v0.x = fmaxf(v0.x + bb.x, 0.f); v0.y = fmaxf(v0.y + bb.y, 0.f);
                v1.x = fmaxf(v1.x + bb.x, 0.f); v1.y = fmaxf(v1.y + bb.y, 0.f);
                uint2 w0, w1;
                split_pack(v0.x, v0.y, w0.x, w0.y);
                split_pack(v1.x, v1.y, w1.x, w1.y);
                uint32_t* P = (uint32_t*)Cout;
                *(uint2*)(P + (size_t)row * N + col)       = w0;
                *(uint2*)(P + (size_t)(row + 8) * N + col) = w1;
            } else {
                float* C = (float*)Cout;
                *(float2*)(C + (size_t)row * N + col)       = v0;
                *(float2*)(C + (size_t)(row + 8) * N + col) = v1;
            }
        }
    }
}

// ---------------- attention scalars ----------------
__global__ void al1_kernel(const float* __restrict__ a_src,
                           const float* __restrict__ a_dst)
{
    int gw = (blockIdx.x * blockDim.x + threadIdx.x) >> 5;
    if (gw >= NN) return;
    int lane = threadIdx.x & 31;
    const float4* row = (const float4*)(g_g1 + (size_t)gw * DD);
    const float4* as4 = (const float4*)a_src;
    const float4* ad4 = (const float4*)a_dst;
    float s0 = 0.f, s1 = 0.f, d0 = 0.f, d1 = 0.f;
    for (int c = lane; c < 128; c += 32) {
        float4 v = row[c];
        float4 a = as4[c];
        float4 b = ad4[c];
        float sv = v.x * a.x + v.y * a.y + v.z * a.z + v.w * a.w;
        float dv = v.x * b.x + v.y * b.y + v.z * b.z + v.w * b.w;
        if (c < 64) { s0 += sv; d0 += dv; } else { s1 += sv; d1 += dv; }
    }
    #pragma unroll
    for (int o = 16; o; o >>= 1) {
        s0 += __shfl_down_sync(0xffffffffu, s0, o);
        s1 += __shfl_down_sync(0xffffffffu, s1, o);
        d0 += __shfl_down_sync(0xffffffffu, d0, o);
        d1 += __shfl_down_sync(0xffffffffu, d1, o);
    }
    if (lane == 0) {
        g_al1[gw * 4 + 0] = s0;
        g_al1[gw * 4 + 1] = s1;
        g_al1[gw * 4 + 2] = d0;
        g_al1[gw * 4 + 3] = d1;
    }
}

__global__ void al2_kernel(const float* __restrict__ a_src,
                           const float* __restrict__ a_dst)
{
    int gw = (blockIdx.x * blockDim.x + threadIdx.x) >> 5;
    if (gw >= NN) return;
    int lane = threadIdx.x & 31;
    const float4* row = (const float4*)(g_g2 + (size_t)gw * DD);
    const float4* as4 = (const float4*)a_src;
    const float4* ad4 = (const float4*)a_dst;
    float s = 0.f, d = 0.f;
    for (int c = lane; c < 128; c += 32) {
        float4 v = row[c];
        float4 a = as4[c];
        float4 b = ad4[c];
        s += v.x * a.x + v.y * a.y + v.z * a.z + v.w * a.w;
        d += v.x * b.x + v.y * b.y + v.z * b.z + v.w * b.w;
    }
    #pragma unroll
    for (int o = 16; o; o >>= 1) {
        s += __shfl_down_sync(0xffffffffu, s, o);
        d += __shfl_down_sync(0xffffffffu, d, o);
    }
    if (lane == 0) {
        g_al2[gw * 2 + 0] = s;
        g_al2[gw * 2 + 1] = d;
    }
}

__device__ __forceinline__ float lrelu(float x) {
    return x > 0.f ? x : NEG_SLOPE * x;
}

// ---------------- edge softmax (warp per node, incl. self loop) ----------------
__global__ void alpha1_kernel() {
    int n = (blockIdx.x * blockDim.x + threadIdx.x) >> 5;
    if (n >= NN) return;
    int lane = threadIdx.x & 31;
    int o = g_off[n];
    int cnt = g_off[n + 1] - o;
    float dd0 = g_al1[n * 4 + 2];
    float dd1 = g_al1[n * 4 + 3];

    float m0 = -1e30f, m1 = -1e30f;
    for (int i = lane; i <= cnt; i += 32) {
        int s = (i < cnt) ? g_esrc[o + i] : n;
        float e0 = lrelu(g_al1[s * 4 + 0] + dd0);
        float e1 = lrelu(g_al1[s * 4 + 1] + dd1);
        m0 = fmaxf(m0, e0);
        m1 = fmaxf(m1, e1);
    }
    #pragma unroll
    for (int x = 16; x; x >>= 1) {
        m0 = fmaxf(m0, __shfl_xor_sync(0xffffffffu, m0, x));
        m1 = fmaxf(m1, __shfl_xor_sync(0xffffffffu, m1, x));
    }
    float sum0 = 0.f, sum1 = 0.f;
    for (int i = lane; i <= cnt; i += 32) {
        int s = (i < cnt) ? g_esrc[o + i] : n;
        sum0 += expf(lrelu(g_al1[s * 4 + 0] + dd0) - m0);
        sum1 += expf(lrelu(g_al1[s * 4 + 1] + dd1) - m1);
    }
    #pragma unroll
    for (int x = 16; x; x >>= 1) {
        sum0 += __shfl_xor_sync(0xffffffffu, sum0, x);
        sum1 += __shfl_xor_sync(0xffffffffu, sum1, x);
    }
    float inv0 = 1.f / (sum0 + 1e-16f);
    float inv1 = 1.f / (sum1 + 1e-16f);
    for (int i = lane; i <= cnt; i += 32) {
        int s = (i < cnt) ? g_esrc[o + i] : n;
        float a0 = expf(lrelu(g_al1[s * 4 + 0] + dd0) - m0) * inv0;
        float a1 = expf(lrelu(g_al1[s * 4 + 1] + dd1) - m1) * inv1;
        if (i < cnt) {
            g_alpha1[(size_t)(o + i) * 2 + 0] = a0;
            g_alpha1[(size_t)(o + i) * 2 + 1] = a1;
        } else {
            g_salpha1[n * 2 + 0] = a0;
            g_salpha1[n * 2 + 1] = a1;
        }
    }
}

__global__ void alpha2_kernel() {
    int n = (blockIdx.x * blockDim.x + threadIdx.x) >> 5;
    if (n >= NN) return;
    int lane = threadIdx.x & 31;
    int o = g_off[n];
    int cnt = g_off[n + 1] - o;
    float dd = g_al2[n * 2 + 1];

    float m = -1e30f;
    for (int i = lane; i <= cnt; i += 32) {
        int s = (i < cnt) ? g_esrc[o + i] : n;
        m = fmaxf(m, lrelu(g_al2[s * 2] + dd));
    }
    #pragma unroll
    for (int x = 16; x; x >>= 1)
        m = fmaxf(m, __shfl_xor_sync(0xffffffffu, m, x));
    float sum = 0.f;
    for (int i = lane; i <= cnt; i += 32) {
        int s = (i < cnt) ? g_esrc[o + i] : n;
        sum += expf(lrelu(g_al2[s * 2] + dd) - m);
    }
    #pragma unroll
    for (int x = 16; x; x >>= 1)
        sum += __shfl_xor_sync(0xffffffffu, sum, x);
    float inv = 1.f / (sum + 1e-16f);
    for (int i = lane; i <= cnt; i += 32) {
        int s = (i < cnt) ? g_esrc[o + i] : n;
        float a = expf(lrelu(g_al2[s * 2] + dd) - m) * inv;
        if (i < cnt) g_alpha2[o + i] = a;
        else g_salpha2[n] = a;
    }
}

// ---------------- aggregation (block of 128 threads per node) ----------------
// agg1: gathers g_g1 fp32 rows, outputs PACKED split-bf16 h1 (GEMM3 input).
__global__ __launch_bounds__(128) void agg1_kernel(const float* __restrict__ b1) {
    int n = blockIdx.x;
    int tid = threadIdx.x;
    int o = g_off[n];
    int cnt = g_off[n + 1] - o;
    int head = tid >> 6;

    __shared__ int   ssrc[128];
    __shared__ float sal[128 * 2];

    float4 acc = make_float4(0.f, 0.f, 0.f, 0.f);
    for (int base = 0; base < cnt; base += 128) {
        int m = min(128, cnt - base);
        if (tid < m) {
            ssrc[tid] = g_esrc[o + base + tid];
            sal[tid * 2 + 0] = g_alpha1[(size_t)(o + base + tid) * 2 + 0];
            sal[tid * 2 + 1] = g_alpha1[(size_t)(o + base + tid) * 2 + 1];
        }
        __syncthreads();
        for (int j = 0; j < m; j++) {
            float a = sal[j * 2 + head];
            const float4* r = (const float4*)(g_g1 + (size_t)ssrc[j] * DD);
            float4 v = r[tid];
            acc.x = fmaf(a, v.x, acc.x);
            acc.y = fmaf(a, v.y, acc.y);
            acc.z = fmaf(a, v.z, acc.z);
            acc.w = fmaf(a, v.w, acc.w);
        }
        __syncthreads();
    }
    {
        float a = g_salpha1[n * 2 + head];
        float4 v = ((const float4*)(g_g1 + (size_t)n * DD))[tid];
        acc.x = fmaf(a, v.x, acc.x);
        acc.y = fmaf(a, v.y, acc.y);
        acc.z = fmaf(a, v.z, acc.z);
        acc.w = fmaf(a, v.w, acc.w);
    }
    float4 bb = ((const float4*)b1)[tid];
    acc.x = fmaxf(acc.x + bb.x, 0.f);
    acc.y = fmaxf(acc.y + bb.y, 0.f);
    acc.z = fmaxf(acc.z + bb.z, 0.f);
    acc.w = fmaxf(acc.w + bb.w, 0.f);
    uint4 w;
    split_pack(acc.x, acc.y, w.x, w.y);
    split_pack(acc.z, acc.w, w.z, w.w);
    *(uint4*)(g_h1p + (size_t)n * DD + 4 * tid) = w;
}

__global__ __launch_bounds__(128) void agg2_kernel(const float* __restrict__ b2,
                                                   float* __restrict__ out) {
    int n = blockIdx.x;
    int tid = threadIdx.x;
    int o = g_off[n];
    int cnt = g_off[n + 1] - o;

    __shared__ int   ssrc[128];
    __shared__ float sal[128];

    float4 acc = make_float4(0.f, 0.f, 0.f, 0.f);
    for (int base = 0; base < cnt; base += 128) {
        int m = min(128, cnt - base);
        if (tid < m) {
            ssrc[tid] = g_esrc[o + base + tid];
            sal[tid] = g_alpha2[o + base + tid];
        }
        __syncthreads();
        for (int j = 0; j < m; j++) {
            float a = sal[j];
            const float4* r = (const float4*)(g_g2 + (size_t)ssrc[j] * DD);
            float4 v = r[tid];
            acc.x = fmaf(a, v.x, acc.x);
            acc.y = fmaf(a, v.y, acc.y);
            acc.z = fmaf(a, v.z, acc.z);
            acc.w = fmaf(a, v.w, acc.w);
        }
        __syncthreads();
    }
    {
        float a = g_salpha2[n];
        float4 v = ((const float4*)(g_g2 + (size_t)n * DD))[tid];
        acc.x = fmaf(a, v.x, acc.x);
        acc.y = fmaf(a, v.y, acc.y);
        acc.z = fmaf(a, v.z, acc.z);
        acc.w = fmaf(a, v.w, acc.w);
    }
    float4 bb = ((const float4*)b2)[tid];
    acc.x = fmaxf(acc.x + bb.x, 0.f);
    acc.y = fmaxf(acc.y + bb.y, 0.f);
    acc.z = fmaxf(acc.z + bb.z, 0.f);
    acc.w = fmaxf(acc.w + bb.w, 0.f);
    ((float4*)(out + (size_t)n * DD))[tid] = acc;
}

// ---------------- launcher ----------------
template <typename T>
static T* sym_p(const void* sym) {
    void* p = nullptr;
    cudaGetSymbolAddress(&p, sym);
    return (T*)p;
}

extern "C" void kernel_launch(void* const* d_in, const int* in_sizes, int n_in,
                              void* d_out, int out_size) {
    const float* x      = (const float*)d_in[0];
    const int*   adj    = (const int*)d_in[1];   // JAX x64-disabled: int32
    const float* W_fc   = (const float*)d_in[2];
    const float* b_fc   = (const float*)d_in[3];
    const float* W1     = (const float*)d_in[4];
    const float* a1_src = (const float*)d_in[5];
    const float* a1_dst = (const float*)d_in[6];
    const float* b1     = (const float*)d_in[7];
    const float* W2     = (const float*)d_in[8];
    const float* a2_src = (const float*)d_in[9];
    const float* a2_dst = (const float*)d_in[10];
    const float* b2     = (const float*)d_in[11];
    float* out = (float*)d_out;

    uint32_t* p_xp  = sym_p<uint32_t>(g_xp);
    uint32_t* p_h0p = sym_p<uint32_t>(g_h0p);
    uint32_t* p_h1p = sym_p<uint32_t>(g_h1p);
    float*    p_g1  = sym_p<float>(g_g1);
    float*    p_g2  = sym_p<float>(g_g2);
    uint4*    p_wfc = sym_p<uint4>(g_wfcp);
    uint4*    p_w1  = sym_p<uint4>(g_w1p);
    uint4*    p_w2  = sym_p<uint4>(g_w2p);

    // Pre-pack inputs & weights (split once, reuse across all tiles)
    pack_a_kernel<<<(NN * H1C / 2 + 255) / 256, 256>>>(x, p_xp, NN * H1C / 2);
    pack_b_kernel<<<((H1C / 4) * H1C + 255) / 256, 256>>>(W_fc, p_wfc, H1C, H1C);
    pack_b_kernel<<<((H1C / 4) * DD + 255) / 256, 256>>>(W1, p_w1, H1C, DD);
    pack_b_kernel<<<((DD / 4) * DD + 255) / 256, 256>>>(W2, p_w2, DD, DD);

    // CSR build
    zero_kernel<<<(NN + 255) / 256, 256>>>();
    count_kernel<<<(EE + 255) / 256, 256>>>(adj);
    scan_kernel<<<1, 256>>>();
    scatter_kernel<<<(EE + 255) / 256, 256>>>(adj);

    // fc + relu -> packed h0   [16384,256]
    {
        dim3 grid(H1C / 128, NN / 128);
        tgemm_p_kernel<1><<<grid, 256>>>(p_xp, p_wfc, b_fc, p_h0p, NN, H1C, H1C);
    }
    // gat1 linear: g1 = h0 @ W1 (fp32 out)   [16384,512]
    {
        dim3 grid(DD / 128, NN / 128);
        tgemm_p_kernel<0><<<grid, 256>>>(p_h0p, p_w1, nullptr, p_g1, NN, DD, H1C);
    }
    al1_kernel<<<(NN * 32 + 255) / 256, 256>>>(a1_src, a1_dst);
    alpha1_kernel<<<(NN * 32 + 255) / 256, 256>>>();
    agg1_kernel<<<NN, 128>>>(b1);          // -> packed h1

    // gat2 linear: g2 = h1 @ W2 (fp32 out)   [16384,512]
    {
        dim3 grid(DD / 128, NN / 128);
        tgemm_p_kernel<0><<<grid, 256>>>(p_h1p, p_w2, nullptr, p_g2, NN, DD, DD);
    }
    al2_kernel<<<(NN * 32 + 255) / 256, 256>>>(a2_src, a2_dst);
    alpha2_kernel<<<(NN * 32 + 255) / 256, 256>>>();
    agg2_kernel<<<NN, 128>>>(b2, out);
}